// round 1
// baseline (speedup 1.0000x reference)
#include <cuda_runtime.h>
#include <math.h>

// DeepLK inverse-compositional LK homography solve.
// img, temp: [8,1,512,512] f32. Output: p [8,8,1] then H [8,3,3] = 136 floats.

#define WI 512
#define HI 512
#define NPIX (WI*HI)
#define NB 8
#define NBLK_R 256   // residual partial-reduction blocks per batch
#define NBLK_H 64    // Gram partial-reduction blocks per batch
#define NITER 10

// persistent scratch / state (no allocations allowed)
__device__ double g_partR[NB][NBLK_R][8];
__device__ double g_partH[NB][NBLK_H][36];
__device__ double g_invH[NB][8][8];
__device__ float  g_p[NB][8];
__device__ float  g_dp[NB][8];

__device__ __forceinline__ void grad_td(const float* __restrict__ T, int x, int y,
                                        float& gx, float& gy) {
    int xm = x > 0      ? x - 1 : 0;
    int xp = x < WI - 1 ? x + 1 : WI - 1;
    int ym = y > 0      ? y - 1 : 0;
    int yp = y < HI - 1 ? y + 1 : HI - 1;
    gx = 0.5f * (T[y * WI + xp] - T[y * WI + xm]);
    gy = 0.5f * (T[yp * WI + x] - T[ym * WI + x]);
}

// ---------------------------------------------------------------------------
// Gram matrix Hm = J^T J  (36 unique entries, symmetric 8x8), per batch.
// ---------------------------------------------------------------------------
__global__ void __launch_bounds__(256) kGram(const float* __restrict__ temp) {
    int b = blockIdx.y;
    const float* T = temp + (size_t)b * NPIX;
    double acc[36];
#pragma unroll
    for (int c = 0; c < 36; c++) acc[c] = 0.0;

    for (int i = blockIdx.x * 256 + threadIdx.x; i < NPIX; i += NBLK_H * 256) {
        int x = i & (WI - 1), y = i >> 9;
        float gx, gy;
        grad_td(T, x, y, gx, gy);
        float X = (float)x - 255.5f, Y = (float)y - 255.5f;
        float a[8];
        a[0] = X * gx; a[1] = Y * gx; a[2] = gx;
        a[3] = X * gy; a[4] = Y * gy; a[5] = gy;
        a[6] = -X * X * gx - X * Y * gy;
        a[7] = -X * Y * gx - Y * Y * gy;
        int c = 0;
#pragma unroll
        for (int ii = 0; ii < 8; ii++)
#pragma unroll
            for (int jj = ii; jj < 8; jj++)
                acc[c++] += (double)a[ii] * (double)a[jj];
    }

    __shared__ double sred[256];
    for (int c = 0; c < 36; c++) {
        sred[threadIdx.x] = acc[c];
        __syncthreads();
        for (int s = 128; s > 0; s >>= 1) {
            if (threadIdx.x < s) sred[threadIdx.x] += sred[threadIdx.x + s];
            __syncthreads();
        }
        if (threadIdx.x == 0) g_partH[b][blockIdx.x][c] = sred[0];
        __syncthreads();
    }
}

// ---------------------------------------------------------------------------
// Reduce Gram partials, invert 8x8 (double Gauss-Jordan w/ partial pivoting),
// and initialize p = 0, dp = 1.
// ---------------------------------------------------------------------------
__global__ void kInvInit() {
    int b = blockIdx.x;
    __shared__ double sH[36];
    __shared__ double A[8][16];
    int t = threadIdx.x;
    if (t < 36) {
        double s = 0.0;
        for (int i = 0; i < NBLK_H; i++) s += g_partH[b][i][t];
        sH[t] = s;
    }
    if (t < 8) { g_p[b][t] = 0.0f; g_dp[b][t] = 1.0f; }
    __syncthreads();
    if (t == 0) {
        int c = 0;
        for (int i = 0; i < 8; i++)
            for (int j = i; j < 8; j++) { A[i][j] = sH[c]; A[j][i] = sH[c]; c++; }
        for (int i = 0; i < 8; i++)
            for (int j = 0; j < 8; j++) A[i][8 + j] = (i == j) ? 1.0 : 0.0;
        for (int col = 0; col < 8; col++) {
            int piv = col; double mx = fabs(A[col][col]);
            for (int r = col + 1; r < 8; r++) {
                double v = fabs(A[r][col]);
                if (v > mx) { mx = v; piv = r; }
            }
            if (piv != col)
                for (int j = 0; j < 16; j++) {
                    double tmp = A[col][j]; A[col][j] = A[piv][j]; A[piv][j] = tmp;
                }
            double inv = 1.0 / A[col][col];
            for (int j = 0; j < 16; j++) A[col][j] *= inv;
            for (int r = 0; r < 8; r++)
                if (r != col) {
                    double f = A[r][col];
                    for (int j = 0; j < 16; j++) A[r][j] -= f * A[col][j];
                }
        }
        for (int i = 0; i < 8; i++)
            for (int j = 0; j < 8; j++) g_invH[b][i][j] = A[i][8 + j];
    }
}

// ---------------------------------------------------------------------------
// Per iteration: warp coords by H(p), bilinear sample img (zeros padding),
// residual r = sample - temp*mask, partial-reduce v = J^T r (8 doubles/block).
// ---------------------------------------------------------------------------
__global__ void __launch_bounds__(256) kResidual(const float* __restrict__ img,
                                                 const float* __restrict__ temp) {
    int b = blockIdx.y;
    const float* I = img  + (size_t)b * NPIX;
    const float* T = temp + (size_t)b * NPIX;

    __shared__ float sp[8];
    if (threadIdx.x < 8) sp[threadIdx.x] = g_p[b][threadIdx.x];
    __syncthreads();
    float p0 = sp[0], p1 = sp[1], p2 = sp[2], p3 = sp[3];
    float p4 = sp[4], p5 = sp[5], p6 = sp[6], p7 = sp[7];

    double acc[8];
#pragma unroll
    for (int c = 0; c < 8; c++) acc[c] = 0.0;

    const float BND = 0.99609375f;  // 1 - 2/512 exactly

    for (int i = blockIdx.x * 256 + threadIdx.x; i < NPIX; i += NBLK_R * 256) {
        int x = i & (WI - 1), y = i >> 9;
        float X = (float)x - 255.5f, Y = (float)y - 255.5f;

        float den = p6 * X + p7 * Y + 1.0f;        // p6=p7=0 always -> 1.0
        float Xw = ((1.0f + p0) * X + p1 * Y + p2) / den + 255.5f;
        float Yw = (p3 * X + (1.0f + p4) * Y + p5) / den + 255.5f;

        // bilinear, zeros padding, align_corners semantics
        float x0f = floorf(Xw), y0f = floorf(Yw);
        float wx = Xw - x0f, wy = Yw - y0f;
        float x0c = fminf(fmaxf(x0f, -2.0f), 513.0f);   // safe int conversion;
        float y0c = fminf(fmaxf(y0f, -2.0f), 513.0f);   // clamped range still invalid
        int x0 = (int)x0c, y0 = (int)y0c;
        bool vx0 = (x0 >= 0) && (x0 <= WI - 1);
        bool vx1 = (x0 + 1 >= 0) && (x0 + 1 <= WI - 1);
        bool vy0 = (y0 >= 0) && (y0 <= HI - 1);
        bool vy1 = (y0 + 1 >= 0) && (y0 + 1 <= HI - 1);
        int xi0 = min(max(x0, 0), WI - 1), xi1 = min(max(x0 + 1, 0), WI - 1);
        int yi0 = min(max(y0, 0), HI - 1), yi1 = min(max(y0 + 1, 0), HI - 1);

        float v = 0.0f;
        if (vx0 && vy0) v += I[yi0 * WI + xi0] * ((1.0f - wx) * (1.0f - wy));
        if (vx1 && vy0) v += I[yi0 * WI + xi1] * (wx * (1.0f - wy));
        if (vx0 && vy1) v += I[yi1 * WI + xi0] * ((1.0f - wx) * wy);
        if (vx1 && vy1) v += I[yi1 * WI + xi1] * (wx * wy);

        float xn = Xw / 255.5f - 1.0f;
        float yn = Yw / 255.5f - 1.0f;
        float mask = (xn > -BND && xn < BND && yn > -BND && yn < BND) ? 1.0f : 0.0f;

        float r = v - T[i] * mask;

        float gx, gy;
        grad_td(T, x, y, gx, gy);

        double rd = (double)r;
        float a0 = X * gx, a1 = Y * gx, a3 = X * gy, a4 = Y * gy;
        float a6 = -X * X * gx - X * Y * gy;
        float a7 = -X * Y * gx - Y * Y * gy;
        acc[0] += (double)a0 * rd;
        acc[1] += (double)a1 * rd;
        acc[2] += (double)gx * rd;
        acc[3] += (double)a3 * rd;
        acc[4] += (double)a4 * rd;
        acc[5] += (double)gy * rd;
        acc[6] += (double)a6 * rd;
        acc[7] += (double)a7 * rd;
    }

    // deterministic block reduction: warp shuffle then cross-warp
    unsigned FULL = 0xffffffffu;
#pragma unroll
    for (int c = 0; c < 8; c++)
        for (int off = 16; off > 0; off >>= 1)
            acc[c] += __shfl_down_sync(FULL, acc[c], off);

    __shared__ double swp[8][8];
    int wid = threadIdx.x >> 5, lane = threadIdx.x & 31;
    if (lane == 0)
#pragma unroll
        for (int c = 0; c < 8; c++) swp[wid][c] = acc[c];
    __syncthreads();
    if (threadIdx.x < 8) {
        double s = 0.0;
#pragma unroll
        for (int w = 0; w < 8; w++) s += swp[w][threadIdx.x];
        g_partR[b][blockIdx.x][threadIdx.x] = s;
    }
}

// ---------------------------------------------------------------------------
// Sum partials, dp = invH * v, zero dp[6:8], gate on ||dp_prev|| > 1e-3,
// p -= gate*dp.
// ---------------------------------------------------------------------------
__global__ void kUpdate() {
    int b = blockIdx.x;
    __shared__ double sv[8];
    int wid = threadIdx.x >> 5, lane = threadIdx.x & 31;
    double s = 0.0;
    for (int i = lane; i < NBLK_R; i += 32) s += g_partR[b][i][wid];
    for (int off = 16; off > 0; off >>= 1)
        s += __shfl_down_sync(0xffffffffu, s, off);
    if (lane == 0) sv[wid] = s;
    __syncthreads();
    if (threadIdx.x == 0) {
        double n2 = 0.0;
        for (int j = 0; j < 8; j++) { double d = (double)g_dp[b][j]; n2 += d * d; }
        bool gate = sqrt(n2) > 1e-3;
        for (int i = 0; i < 8; i++) {
            double d = 0.0;
            for (int j = 0; j < 8; j++) d += g_invH[b][i][j] * sv[j];
            if (i >= 6) d = 0.0;                 // no projective update
            float dpf = gate ? (float)d : 0.0f;
            g_dp[b][i] = dpf;
            g_p[b][i] = g_p[b][i] - dpf;
        }
    }
}

// ---------------------------------------------------------------------------
// Emit output: p [B,8] then H [B,3,3].
// ---------------------------------------------------------------------------
__global__ void kFinalize(float* __restrict__ out, int out_size) {
    int t = threadIdx.x;
    if (t < NB * 8 && t < out_size) out[t] = g_p[t >> 3][t & 7];
    if (t < NB * 9) {
        int b = t / 9, e = t % 9;
        float* p = g_p[b];
        float m[9] = {1.0f + p[0], p[1], p[2],
                      p[3], 1.0f + p[4], p[5],
                      p[6], p[7], 1.0f};
        int idx = NB * 8 + t;
        if (idx < out_size) out[idx] = m[e];
    }
}

extern "C" void kernel_launch(void* const* d_in, const int* in_sizes, int n_in,
                              void* d_out, int out_size) {
    const float* img  = (const float*)d_in[0];
    const float* temp = (const float*)d_in[1];
    float* out = (float*)d_out;

    kGram<<<dim3(NBLK_H, NB), 256>>>(temp);
    kInvInit<<<NB, 64>>>();
    for (int it = 0; it < NITER; it++) {
        kResidual<<<dim3(NBLK_R, NB), 256>>>(img, temp);
        kUpdate<<<NB, 256>>>();
    }
    kFinalize<<<1, 128>>>(out, out_size);
}

// round 2
// speedup vs baseline: 4.6749x; 4.6749x over previous
#include <cuda_runtime.h>
#include <math.h>

// DeepLK inverse-compositional LK homography solve.
// img, temp: [8,1,512,512] f32. Output: p [8,8,1] then H [8,3,3] = 136 floats.

#define WI 512
#define HI 512
#define NPIX (WI*HI)
#define NB 8
#define NBLK_R 128   // residual partial-reduction blocks per batch
#define NBLK_H 64    // Gram partial-reduction blocks per batch
#define NITER 10

// persistent scratch / state (no allocations allowed)
__device__ float  g_partR[NB][NBLK_R][8];
__device__ float  g_partH[NB][NBLK_H][36];
__device__ double g_invH[NB][8][8];
__device__ float  g_p[NB][8];
__device__ float  g_dp[NB][8];

__device__ __forceinline__ void grad_td(const float* __restrict__ T, int x, int y,
                                        float& gx, float& gy) {
    int xm = x > 0      ? x - 1 : 0;
    int xp = x < WI - 1 ? x + 1 : WI - 1;
    int ym = y > 0      ? y - 1 : 0;
    int yp = y < HI - 1 ? y + 1 : HI - 1;
    gx = 0.5f * (T[y * WI + xp] - T[y * WI + xm]);
    gy = 0.5f * (T[yp * WI + x] - T[ym * WI + x]);
}

// ---------------------------------------------------------------------------
// Gram matrix Hm = J^T J  (36 unique entries, symmetric 8x8), per batch.
// f32 accumulation (matches JAX reference, which does einsum in f32).
// ---------------------------------------------------------------------------
__global__ void __launch_bounds__(256) kGram(const float* __restrict__ temp) {
    int b = blockIdx.y;
    const float* T = temp + (size_t)b * NPIX;
    float acc[36];
#pragma unroll
    for (int c = 0; c < 36; c++) acc[c] = 0.0f;

    for (int i = blockIdx.x * 256 + threadIdx.x; i < NPIX; i += NBLK_H * 256) {
        int x = i & (WI - 1), y = i >> 9;
        float gx, gy;
        grad_td(T, x, y, gx, gy);
        float X = (float)x - 255.5f, Y = (float)y - 255.5f;
        float a[8];
        a[0] = X * gx; a[1] = Y * gx; a[2] = gx;
        a[3] = X * gy; a[4] = Y * gy; a[5] = gy;
        a[6] = -X * X * gx - X * Y * gy;
        a[7] = -X * Y * gx - Y * Y * gy;
        int c = 0;
#pragma unroll
        for (int ii = 0; ii < 8; ii++)
#pragma unroll
            for (int jj = ii; jj < 8; jj++)
                acc[c++] += a[ii] * a[jj];
    }

    // warp tree then cross-warp tree, all f32 (deterministic)
    unsigned FULL = 0xffffffffu;
#pragma unroll
    for (int c = 0; c < 36; c++)
        for (int off = 16; off > 0; off >>= 1)
            acc[c] += __shfl_down_sync(FULL, acc[c], off);

    __shared__ float swp[8][36];
    int wid = threadIdx.x >> 5, lane = threadIdx.x & 31;
    if (lane == 0)
#pragma unroll
        for (int c = 0; c < 36; c++) swp[wid][c] = acc[c];
    __syncthreads();
    if (threadIdx.x < 36) {
        float s = 0.0f;
#pragma unroll
        for (int w = 0; w < 8; w++) s += swp[w][threadIdx.x];
        g_partH[b][blockIdx.x][threadIdx.x] = s;
    }
}

// ---------------------------------------------------------------------------
// Reduce Gram partials (double), invert 8x8 (double Gauss-Jordan w/ partial
// pivoting), and initialize p = 0, dp = 1.
// ---------------------------------------------------------------------------
__global__ void kInvInit() {
    int b = blockIdx.x;
    __shared__ double sH[36];
    __shared__ double A[8][16];
    int t = threadIdx.x;
    if (t < 36) {
        double s = 0.0;
        for (int i = 0; i < NBLK_H; i++) s += (double)g_partH[b][i][t];
        sH[t] = s;
    }
    if (t < 8) { g_p[b][t] = 0.0f; g_dp[b][t] = 1.0f; }
    __syncthreads();
    if (t == 0) {
        int c = 0;
        for (int i = 0; i < 8; i++)
            for (int j = i; j < 8; j++) { A[i][j] = sH[c]; A[j][i] = sH[c]; c++; }
        for (int i = 0; i < 8; i++)
            for (int j = 0; j < 8; j++) A[i][8 + j] = (i == j) ? 1.0 : 0.0;
        for (int col = 0; col < 8; col++) {
            int piv = col; double mx = fabs(A[col][col]);
            for (int r = col + 1; r < 8; r++) {
                double v = fabs(A[r][col]);
                if (v > mx) { mx = v; piv = r; }
            }
            if (piv != col)
                for (int j = 0; j < 16; j++) {
                    double tmp = A[col][j]; A[col][j] = A[piv][j]; A[piv][j] = tmp;
                }
            double inv = 1.0 / A[col][col];
            for (int j = 0; j < 16; j++) A[col][j] *= inv;
            for (int r = 0; r < 8; r++)
                if (r != col) {
                    double f = A[r][col];
                    for (int j = 0; j < 16; j++) A[r][j] -= f * A[col][j];
                }
        }
        for (int i = 0; i < 8; i++)
            for (int j = 0; j < 8; j++) g_invH[b][i][j] = A[i][8 + j];
    }
}

// ---------------------------------------------------------------------------
// Per iteration: warp coords by H(p), bilinear sample img (zeros padding),
// residual r = sample - temp*mask, partial-reduce v = J^T r, all f32.
// ---------------------------------------------------------------------------
__global__ void __launch_bounds__(256) kResidual(const float* __restrict__ img,
                                                 const float* __restrict__ temp) {
    int b = blockIdx.y;
    const float* I = img  + (size_t)b * NPIX;
    const float* T = temp + (size_t)b * NPIX;

    __shared__ float sp[8];
    if (threadIdx.x < 8) sp[threadIdx.x] = g_p[b][threadIdx.x];
    __syncthreads();
    float p0 = sp[0], p1 = sp[1], p2 = sp[2], p3 = sp[3];
    float p4 = sp[4], p5 = sp[5], p6 = sp[6], p7 = sp[7];

    float acc[8];
#pragma unroll
    for (int c = 0; c < 8; c++) acc[c] = 0.0f;

    const float BND = 0.99609375f;  // 1 - 2/512 exactly

    for (int i = blockIdx.x * 256 + threadIdx.x; i < NPIX; i += NBLK_R * 256) {
        int x = i & (WI - 1), y = i >> 9;
        float X = (float)x - 255.5f, Y = (float)y - 255.5f;

        float den = p6 * X + p7 * Y + 1.0f;        // p6=p7=0 always -> 1.0
        float Xw = ((1.0f + p0) * X + p1 * Y + p2) / den + 255.5f;
        float Yw = (p3 * X + (1.0f + p4) * Y + p5) / den + 255.5f;

        // bilinear, zeros padding, align_corners semantics
        float x0f = floorf(Xw), y0f = floorf(Yw);
        float wx = Xw - x0f, wy = Yw - y0f;
        float x0c = fminf(fmaxf(x0f, -2.0f), 513.0f);   // safe int conversion
        float y0c = fminf(fmaxf(y0f, -2.0f), 513.0f);
        int x0 = (int)x0c, y0 = (int)y0c;
        bool vx0 = (x0 >= 0) && (x0 <= WI - 1);
        bool vx1 = (x0 + 1 >= 0) && (x0 + 1 <= WI - 1);
        bool vy0 = (y0 >= 0) && (y0 <= HI - 1);
        bool vy1 = (y0 + 1 >= 0) && (y0 + 1 <= HI - 1);
        int xi0 = min(max(x0, 0), WI - 1), xi1 = min(max(x0 + 1, 0), WI - 1);
        int yi0 = min(max(y0, 0), HI - 1), yi1 = min(max(y0 + 1, 0), HI - 1);

        float v = 0.0f;
        if (vx0 && vy0) v += I[yi0 * WI + xi0] * ((1.0f - wx) * (1.0f - wy));
        if (vx1 && vy0) v += I[yi0 * WI + xi1] * (wx * (1.0f - wy));
        if (vx0 && vy1) v += I[yi1 * WI + xi0] * ((1.0f - wx) * wy);
        if (vx1 && vy1) v += I[yi1 * WI + xi1] * (wx * wy);

        float xn = Xw / 255.5f - 1.0f;
        float yn = Yw / 255.5f - 1.0f;
        float mask = (xn > -BND && xn < BND && yn > -BND && yn < BND) ? 1.0f : 0.0f;

        float r = v - T[i] * mask;

        float gx, gy;
        grad_td(T, x, y, gx, gy);

        float a0 = X * gx, a1 = Y * gx, a3 = X * gy, a4 = Y * gy;
        float a6 = -X * X * gx - X * Y * gy;
        float a7 = -X * Y * gx - Y * Y * gy;
        acc[0] += a0 * r;
        acc[1] += a1 * r;
        acc[2] += gx * r;
        acc[3] += a3 * r;
        acc[4] += a4 * r;
        acc[5] += gy * r;
        acc[6] += a6 * r;
        acc[7] += a7 * r;
    }

    // deterministic tree reduction: warp shuffle then cross-warp
    unsigned FULL = 0xffffffffu;
#pragma unroll
    for (int c = 0; c < 8; c++)
        for (int off = 16; off > 0; off >>= 1)
            acc[c] += __shfl_down_sync(FULL, acc[c], off);

    __shared__ float swp[8][8];
    int wid = threadIdx.x >> 5, lane = threadIdx.x & 31;
    if (lane == 0)
#pragma unroll
        for (int c = 0; c < 8; c++) swp[wid][c] = acc[c];
    __syncthreads();
    if (threadIdx.x < 8) {
        float s = 0.0f;
#pragma unroll
        for (int w = 0; w < 8; w++) s += swp[w][threadIdx.x];
        g_partR[b][blockIdx.x][threadIdx.x] = s;
    }
}

// ---------------------------------------------------------------------------
// Sum partials (double), dp = invH * v, zero dp[6:8], gate on
// ||dp_prev|| > 1e-3, p -= gate*dp.   Warp w handles channel w.
// ---------------------------------------------------------------------------
__global__ void kUpdate() {
    int b = blockIdx.x;
    __shared__ double sv[8];
    int wid = threadIdx.x >> 5, lane = threadIdx.x & 31;
    double s = 0.0;
    for (int i = lane; i < NBLK_R; i += 32) s += (double)g_partR[b][i][wid];
    for (int off = 16; off > 0; off >>= 1)
        s += __shfl_down_sync(0xffffffffu, s, off);
    if (lane == 0) sv[wid] = s;
    __syncthreads();
    if (threadIdx.x == 0) {
        double n2 = 0.0;
        for (int j = 0; j < 8; j++) { double d = (double)g_dp[b][j]; n2 += d * d; }
        bool gate = sqrt(n2) > 1e-3;
        for (int i = 0; i < 8; i++) {
            double d = 0.0;
            for (int j = 0; j < 8; j++) d += g_invH[b][i][j] * sv[j];
            if (i >= 6) d = 0.0;                 // no projective update
            float dpf = gate ? (float)d : 0.0f;
            g_dp[b][i] = dpf;
            g_p[b][i] = g_p[b][i] - dpf;
        }
    }
}

// ---------------------------------------------------------------------------
// Emit output: p [B,8] then H [B,3,3].
// ---------------------------------------------------------------------------
__global__ void kFinalize(float* __restrict__ out, int out_size) {
    int t = threadIdx.x;
    if (t < NB * 8 && t < out_size) out[t] = g_p[t >> 3][t & 7];
    if (t < NB * 9) {
        int b = t / 9, e = t % 9;
        float* p = g_p[b];
        float m[9] = {1.0f + p[0], p[1], p[2],
                      p[3], 1.0f + p[4], p[5],
                      p[6], p[7], 1.0f};
        int idx = NB * 8 + t;
        if (idx < out_size) out[idx] = m[e];
    }
}

extern "C" void kernel_launch(void* const* d_in, const int* in_sizes, int n_in,
                              void* d_out, int out_size) {
    const float* img  = (const float*)d_in[0];
    const float* temp = (const float*)d_in[1];
    float* out = (float*)d_out;

    kGram<<<dim3(NBLK_H, NB), 256>>>(temp);
    kInvInit<<<NB, 64>>>();
    for (int it = 0; it < NITER; it++) {
        kResidual<<<dim3(NBLK_R, NB), 256>>>(img, temp);
        kUpdate<<<NB, 256>>>();
    }
    kFinalize<<<1, 128>>>(out, out_size);
}

// round 3
// speedup vs baseline: 5.4902x; 1.1744x over previous
#include <cuda_runtime.h>
#include <math.h>

// DeepLK inverse-compositional LK homography solve.
// img, temp: [8,1,512,512] f32. Output: p [8,8,1] then H [8,3,3] = 136 floats.

#define WI 512
#define HI 512
#define NPIX (WI*HI)
#define NQUAD (NPIX/4)
#define NB 8
#define NBLK_R 64    // residual blocks per batch (one wave: 512 blocks total)
#define NBLK_H 64    // Gram partial-reduction blocks per batch
#define NITER 10

// persistent scratch / state (no allocations allowed)
__device__ float        g_partR[NB][NBLK_R][8];
__device__ float        g_partH[NB][NBLK_H][36];
__device__ double       g_invH[NB][8][8];
__device__ float        g_p[NB][8];
__device__ float        g_dp[NB][8];
__device__ unsigned int g_sem[NB];   // zero-initialized; reset to 0 by last block

__device__ __forceinline__ void grad_td(const float* __restrict__ T, int x, int y,
                                        float& gx, float& gy) {
    int xm = x > 0      ? x - 1 : 0;
    int xp = x < WI - 1 ? x + 1 : WI - 1;
    int ym = y > 0      ? y - 1 : 0;
    int yp = y < HI - 1 ? y + 1 : HI - 1;
    gx = 0.5f * (T[y * WI + xp] - T[y * WI + xm]);
    gy = 0.5f * (T[yp * WI + x] - T[ym * WI + x]);
}

// ---------------------------------------------------------------------------
// Gram matrix Hm = J^T J  (36 unique entries, symmetric 8x8), per batch.
// ---------------------------------------------------------------------------
__global__ void __launch_bounds__(256) kGram(const float* __restrict__ temp) {
    int b = blockIdx.y;
    const float* T = temp + (size_t)b * NPIX;
    float acc[36];
#pragma unroll
    for (int c = 0; c < 36; c++) acc[c] = 0.0f;

    for (int i = blockIdx.x * 256 + threadIdx.x; i < NPIX; i += NBLK_H * 256) {
        int x = i & (WI - 1), y = i >> 9;
        float gx, gy;
        grad_td(T, x, y, gx, gy);
        float X = (float)x - 255.5f, Y = (float)y - 255.5f;
        float a[8];
        a[0] = X * gx; a[1] = Y * gx; a[2] = gx;
        a[3] = X * gy; a[4] = Y * gy; a[5] = gy;
        a[6] = -X * X * gx - X * Y * gy;
        a[7] = -X * Y * gx - Y * Y * gy;
        int c = 0;
#pragma unroll
        for (int ii = 0; ii < 8; ii++)
#pragma unroll
            for (int jj = ii; jj < 8; jj++)
                acc[c++] += a[ii] * a[jj];
    }

    unsigned FULL = 0xffffffffu;
#pragma unroll
    for (int c = 0; c < 36; c++)
        for (int off = 16; off > 0; off >>= 1)
            acc[c] += __shfl_down_sync(FULL, acc[c], off);

    __shared__ float swp[8][36];
    int wid = threadIdx.x >> 5, lane = threadIdx.x & 31;
    if (lane == 0)
#pragma unroll
        for (int c = 0; c < 36; c++) swp[wid][c] = acc[c];
    __syncthreads();
    if (threadIdx.x < 36) {
        float s = 0.0f;
#pragma unroll
        for (int w = 0; w < 8; w++) s += swp[w][threadIdx.x];
        g_partH[b][blockIdx.x][threadIdx.x] = s;
    }
}

// ---------------------------------------------------------------------------
// Reduce Gram partials (double), invert 8x8 (double GJ w/ pivoting),
// init p = 0, dp = 1, sem = 0.
// ---------------------------------------------------------------------------
__global__ void kInvInit() {
    int b = blockIdx.x;
    __shared__ double sH[36];
    __shared__ double A[8][16];
    int t = threadIdx.x;
    if (t < 36) {
        double s = 0.0;
        for (int i = 0; i < NBLK_H; i++) s += (double)g_partH[b][i][t];
        sH[t] = s;
    }
    if (t < 8) { g_p[b][t] = 0.0f; g_dp[b][t] = 1.0f; }
    if (t == 0) g_sem[b] = 0u;
    __syncthreads();
    if (t == 0) {
        int c = 0;
        for (int i = 0; i < 8; i++)
            for (int j = i; j < 8; j++) { A[i][j] = sH[c]; A[j][i] = sH[c]; c++; }
        for (int i = 0; i < 8; i++)
            for (int j = 0; j < 8; j++) A[i][8 + j] = (i == j) ? 1.0 : 0.0;
        for (int col = 0; col < 8; col++) {
            int piv = col; double mx = fabs(A[col][col]);
            for (int r = col + 1; r < 8; r++) {
                double v = fabs(A[r][col]);
                if (v > mx) { mx = v; piv = r; }
            }
            if (piv != col)
                for (int j = 0; j < 16; j++) {
                    double tmp = A[col][j]; A[col][j] = A[piv][j]; A[piv][j] = tmp;
                }
            double inv = 1.0 / A[col][col];
            for (int j = 0; j < 16; j++) A[col][j] *= inv;
            for (int r = 0; r < 8; r++)
                if (r != col) {
                    double f = A[r][col];
                    for (int j = 0; j < 16; j++) A[r][j] -= f * A[col][j];
                }
        }
        for (int i = 0; i < 8; i++)
            for (int j = 0; j < 8; j++) g_invH[b][i][j] = A[i][8 + j];
    }
}

// ---------------------------------------------------------------------------
// Per iteration: warp, bilinear sample, residual, J^T r partial reduction,
// then the LAST block of each batch performs the parameter update in-kernel
// (threadfence-reduction pattern). Eliminates the separate kUpdate kernel.
// ---------------------------------------------------------------------------
__global__ void __launch_bounds__(256) kResidual(const float* __restrict__ img,
                                                 const float* __restrict__ temp) {
    int b = blockIdx.y;
    const float* I = img  + (size_t)b * NPIX;
    const float* T = temp + (size_t)b * NPIX;

    __shared__ float sp[8];
    if (threadIdx.x < 8) sp[threadIdx.x] = g_p[b][threadIdx.x];
    __syncthreads();
    float p0 = sp[0], p1 = sp[1], p2 = sp[2];
    float p3 = sp[3], p4 = sp[4], p5 = sp[5];
    // p6 = p7 = 0 exactly (reference zeroes dp[6:8]); den == 1.0 -> skip division

    float acc[8];
#pragma unroll
    for (int c = 0; c < 8; c++) acc[c] = 0.0f;

    const float BND = 0.99609375f;  // 1 - 2/512 exactly

    // each thread handles 4 consecutive pixels (one float4 of T per quad)
    for (int q = blockIdx.x * 256 + threadIdx.x; q < NQUAD; q += NBLK_R * 256) {
        int i = q << 2;
        int x = i & (WI - 1), y = i >> 9;           // x in {0,4,...,508}
        float Yc = (float)y - 255.5f;

        float4 Tc = *reinterpret_cast<const float4*>(T + i);
        int yU = y > 0      ? y - 1 : 0;
        int yD = y < HI - 1 ? y + 1 : HI - 1;
        float4 TU = *reinterpret_cast<const float4*>(T + yU * WI + x);
        float4 TD = *reinterpret_cast<const float4*>(T + yD * WI + x);
        float Tm1 = (x > 0)        ? __ldg(T + i - 1) : Tc.x;
        float Tp4 = (x < WI - 4)   ? __ldg(T + i + 4) : Tc.w;

        float Tca[4] = {Tc.x, Tc.y, Tc.z, Tc.w};
        float gxa[4];
        gxa[0] = 0.5f * (Tc.y - Tm1);
        gxa[1] = 0.5f * (Tc.z - Tc.x);
        gxa[2] = 0.5f * (Tc.w - Tc.y);
        gxa[3] = 0.5f * (Tp4 - Tc.z);
        float gya[4] = {0.5f * (TD.x - TU.x), 0.5f * (TD.y - TU.y),
                        0.5f * (TD.z - TU.z), 0.5f * (TD.w - TU.w)};

#pragma unroll
        for (int j = 0; j < 4; j++) {
            float X = (float)(x + j) - 255.5f;
            float Xw = (1.0f + p0) * X + p1 * Yc + p2 + 255.5f;
            float Yw = p3 * X + (1.0f + p4) * Yc + p5 + 255.5f;

            // bilinear, zeros padding
            float x0f = floorf(Xw), y0f = floorf(Yw);
            float wx = Xw - x0f, wy = Yw - y0f;
            float x0c = fminf(fmaxf(x0f, -2.0f), 513.0f);
            float y0c = fminf(fmaxf(y0f, -2.0f), 513.0f);
            int x0 = (int)x0c, y0 = (int)y0c;
            bool vx0 = (x0 >= 0) && (x0 <= WI - 1);
            bool vx1 = (x0 + 1 >= 0) && (x0 + 1 <= WI - 1);
            bool vy0 = (y0 >= 0) && (y0 <= HI - 1);
            bool vy1 = (y0 + 1 >= 0) && (y0 + 1 <= HI - 1);
            int xi0 = min(max(x0, 0), WI - 1), xi1 = min(max(x0 + 1, 0), WI - 1);
            int yi0 = min(max(y0, 0), HI - 1), yi1 = min(max(y0 + 1, 0), HI - 1);

            float v = 0.0f;
            if (vx0 && vy0) v += __ldg(I + yi0 * WI + xi0) * ((1.0f - wx) * (1.0f - wy));
            if (vx1 && vy0) v += __ldg(I + yi0 * WI + xi1) * (wx * (1.0f - wy));
            if (vx0 && vy1) v += __ldg(I + yi1 * WI + xi0) * ((1.0f - wx) * wy);
            if (vx1 && vy1) v += __ldg(I + yi1 * WI + xi1) * (wx * wy);

            float xn = Xw / 255.5f - 1.0f;
            float yn = Yw / 255.5f - 1.0f;
            float mask = (xn > -BND && xn < BND && yn > -BND && yn < BND) ? 1.0f : 0.0f;

            float r = v - Tca[j] * mask;
            float gx = gxa[j], gy = gya[j];

            acc[0] += (X * gx) * r;
            acc[1] += (Yc * gx) * r;
            acc[2] += gx * r;
            acc[3] += (X * gy) * r;
            acc[4] += (Yc * gy) * r;
            acc[5] += gy * r;
            acc[6] += (-X * X * gx - X * Yc * gy) * r;
            acc[7] += (-X * Yc * gx - Yc * Yc * gy) * r;
        }
    }

    // deterministic tree reduction: warp shuffle then cross-warp
    unsigned FULL = 0xffffffffu;
#pragma unroll
    for (int c = 0; c < 8; c++)
        for (int off = 16; off > 0; off >>= 1)
            acc[c] += __shfl_down_sync(FULL, acc[c], off);

    __shared__ float swp[8][8];
    int wid = threadIdx.x >> 5, lane = threadIdx.x & 31;
    if (lane == 0)
#pragma unroll
        for (int c = 0; c < 8; c++) swp[wid][c] = acc[c];
    __syncthreads();
    if (threadIdx.x < 8) {
        float s = 0.0f;
#pragma unroll
        for (int w = 0; w < 8; w++) s += swp[w][threadIdx.x];
        g_partR[b][blockIdx.x][threadIdx.x] = s;
    }

    // ---- last-block update epilogue ----
    __shared__ bool sIsLast;
    __threadfence();
    __syncthreads();
    if (threadIdx.x == 0) {
        unsigned old = atomicAdd(&g_sem[b], 1u);
        sIsLast = (old == NBLK_R - 1);
    }
    __syncthreads();
    if (!sIsLast) return;

    // load invH into shared in parallel (64 threads, one double each)
    __shared__ double sInv[8][8];
    __shared__ double sv[8];
    if (threadIdx.x < 64)
        sInv[threadIdx.x >> 3][threadIdx.x & 7] =
            g_invH[b][threadIdx.x >> 3][threadIdx.x & 7];

    // warp w reduces channel w over NBLK_R partials (bypass L1: other blocks' data)
    if (wid < 8) {
        double s = 0.0;
        for (int i = lane; i < NBLK_R; i += 32)
            s += (double)__ldcg(&g_partR[b][i][wid]);
        for (int off = 16; off > 0; off >>= 1)
            s += __shfl_down_sync(FULL, s, off);
        if (lane == 0) sv[wid] = s;
    }
    __syncthreads();

    if (threadIdx.x < 8) {
        int i = threadIdx.x;
        double n2 = 0.0;
#pragma unroll
        for (int j = 0; j < 8; j++) { double d = (double)g_dp[b][j]; n2 += d * d; }
        bool gate = sqrt(n2) > 1e-3;
        double d = 0.0;
#pragma unroll
        for (int j = 0; j < 8; j++) d += sInv[i][j] * sv[j];
        if (i >= 6) d = 0.0;                 // no projective update
        float dpf = gate ? (float)d : 0.0f;
        g_dp[b][i] = dpf;
        g_p[b][i] = g_p[b][i] - dpf;
    }
    if (threadIdx.x == 0) g_sem[b] = 0u;     // reset for next iteration/launch
}

// ---------------------------------------------------------------------------
// Emit output: p [B,8] then H [B,3,3].
// ---------------------------------------------------------------------------
__global__ void kFinalize(float* __restrict__ out, int out_size) {
    int t = threadIdx.x;
    if (t < NB * 8 && t < out_size) out[t] = g_p[t >> 3][t & 7];
    if (t < NB * 9) {
        int b = t / 9, e = t % 9;
        float* p = g_p[b];
        float m[9] = {1.0f + p[0], p[1], p[2],
                      p[3], 1.0f + p[4], p[5],
                      p[6], p[7], 1.0f};
        int idx = NB * 8 + t;
        if (idx < out_size) out[idx] = m[e];
    }
}

extern "C" void kernel_launch(void* const* d_in, const int* in_sizes, int n_in,
                              void* d_out, int out_size) {
    const float* img  = (const float*)d_in[0];
    const float* temp = (const float*)d_in[1];
    float* out = (float*)d_out;

    kGram<<<dim3(NBLK_H, NB), 256>>>(temp);
    kInvInit<<<NB, 64>>>();
    for (int it = 0; it < NITER; it++)
        kResidual<<<dim3(NBLK_R, NB), 256>>>(img, temp);
    kFinalize<<<1, 128>>>(out, out_size);
}

// round 4
// speedup vs baseline: 6.8757x; 1.2524x over previous
#include <cuda_runtime.h>
#include <math.h>

// DeepLK inverse-compositional LK homography solve.
// img, temp: [8,1,512,512] f32. Output: p [8,8,1] then H [8,3,3] = 136 floats.

#define WI 512
#define HI 512
#define NPIX (WI*HI)
#define NQUAD (NPIX/4)
#define NB 8
#define NBLK 74      // blocks per batch; grid (74,8) = 592 = 148 SMs * 4 resident
#define NITER 10

// persistent scratch / state (no allocations allowed)
__device__ float        g_partR[NB][NBLK][8];
__device__ float        g_partH[NB][NBLK][36];
__device__ double       g_invH[NB][8][8];
__device__ float        g_p[NB][8];
__device__ float        g_dp[NB][8];
__device__ unsigned int g_sem[NB];
__device__ volatile unsigned int g_gen[NB];

// ---------------------------------------------------------------------------
// Gram matrix Hm = J^T J (36 unique entries), per batch. float4 quads.
// ---------------------------------------------------------------------------
__global__ void __launch_bounds__(256) kGram(const float* __restrict__ temp) {
    int b = blockIdx.y;
    const float* T = temp + (size_t)b * NPIX;
    float acc[36];
#pragma unroll
    for (int c = 0; c < 36; c++) acc[c] = 0.0f;

    for (int q = blockIdx.x * 256 + threadIdx.x; q < NQUAD; q += NBLK * 256) {
        int i = q << 2;
        int x = i & (WI - 1), y = i >> 9;
        float Yc = (float)y - 255.5f;
        float4 Tc = *reinterpret_cast<const float4*>(T + i);
        int yU = y > 0      ? y - 1 : 0;
        int yD = y < HI - 1 ? y + 1 : HI - 1;
        float4 TU = *reinterpret_cast<const float4*>(T + yU * WI + x);
        float4 TD = *reinterpret_cast<const float4*>(T + yD * WI + x);
        float Tm1 = (x > 0)      ? __ldg(T + i - 1) : Tc.x;
        float Tp4 = (x < WI - 4) ? __ldg(T + i + 4) : Tc.w;

        float gxa[4] = {0.5f * (Tc.y - Tm1), 0.5f * (Tc.z - Tc.x),
                        0.5f * (Tc.w - Tc.y), 0.5f * (Tp4 - Tc.z)};
        float gya[4] = {0.5f * (TD.x - TU.x), 0.5f * (TD.y - TU.y),
                        0.5f * (TD.z - TU.z), 0.5f * (TD.w - TU.w)};

#pragma unroll
        for (int j = 0; j < 4; j++) {
            float X = (float)(x + j) - 255.5f;
            float gx = gxa[j], gy = gya[j];
            float s = X * gx + Yc * gy;
            float a[8];
            a[0] = X * gx; a[1] = Yc * gx; a[2] = gx;
            a[3] = X * gy; a[4] = Yc * gy; a[5] = gy;
            a[6] = -X * s; a[7] = -Yc * s;
            int c = 0;
#pragma unroll
            for (int ii = 0; ii < 8; ii++)
#pragma unroll
                for (int jj = ii; jj < 8; jj++)
                    acc[c++] += a[ii] * a[jj];
        }
    }

    unsigned FULL = 0xffffffffu;
#pragma unroll
    for (int c = 0; c < 36; c++)
        for (int off = 16; off > 0; off >>= 1)
            acc[c] += __shfl_down_sync(FULL, acc[c], off);

    __shared__ float swp[8][36];
    int wid = threadIdx.x >> 5, lane = threadIdx.x & 31;
    if (lane == 0)
#pragma unroll
        for (int c = 0; c < 36; c++) swp[wid][c] = acc[c];
    __syncthreads();
    if (threadIdx.x < 36) {
        float s = 0.0f;
#pragma unroll
        for (int w = 0; w < 8; w++) s += swp[w][threadIdx.x];
        g_partH[b][blockIdx.x][threadIdx.x] = s;
    }
}

// ---------------------------------------------------------------------------
// Reduce Gram partials (double), invert 8x8 (double GJ w/ pivoting),
// init p = 0, dp = 1, sem = gen = 0.
// ---------------------------------------------------------------------------
__global__ void kInvInit() {
    int b = blockIdx.x;
    __shared__ double sH[36];
    __shared__ double A[8][16];
    int t = threadIdx.x;
    if (t < 36) {
        double s = 0.0;
        for (int i = 0; i < NBLK; i++) s += (double)g_partH[b][i][t];
        sH[t] = s;
    }
    if (t < 8) { g_p[b][t] = 0.0f; g_dp[b][t] = 1.0f; }
    if (t == 0) { g_sem[b] = 0u; g_gen[b] = 0u; }
    __syncthreads();
    if (t == 0) {
        int c = 0;
        for (int i = 0; i < 8; i++)
            for (int j = i; j < 8; j++) { A[i][j] = sH[c]; A[j][i] = sH[c]; c++; }
        for (int i = 0; i < 8; i++)
            for (int j = 0; j < 8; j++) A[i][8 + j] = (i == j) ? 1.0 : 0.0;
        for (int col = 0; col < 8; col++) {
            int piv = col; double mx = fabs(A[col][col]);
            for (int r = col + 1; r < 8; r++) {
                double v = fabs(A[r][col]);
                if (v > mx) { mx = v; piv = r; }
            }
            if (piv != col)
                for (int j = 0; j < 16; j++) {
                    double tmp = A[col][j]; A[col][j] = A[piv][j]; A[piv][j] = tmp;
                }
            double inv = 1.0 / A[col][col];
            for (int j = 0; j < 16; j++) A[col][j] *= inv;
            for (int r = 0; r < 8; r++)
                if (r != col) {
                    double f = A[r][col];
                    for (int j = 0; j < 16; j++) A[r][j] -= f * A[col][j];
                }
        }
        for (int i = 0; i < 8; i++)
            for (int j = 0; j < 8; j++) g_invH[b][i][j] = A[i][8 + j];
    }
}

// ---------------------------------------------------------------------------
// Persistent kernel: all 10 LK iterations with per-batch software barriers.
// Last block of each batch per iteration reduces partials and updates p.
// Final iteration's last block writes the output.
// ---------------------------------------------------------------------------
__global__ void __launch_bounds__(256, 4) kPersist(const float* __restrict__ img,
                                                   const float* __restrict__ temp,
                                                   float* __restrict__ out,
                                                   int out_size) {
    int b = blockIdx.y;
    const float* I = img  + (size_t)b * NPIX;
    const float* T = temp + (size_t)b * NPIX;
    int tid = threadIdx.x;
    int wid = tid >> 5, lane = tid & 31;
    unsigned FULL = 0xffffffffu;

    __shared__ float  sp[8];
    __shared__ float  swp[8][8];
    __shared__ bool   sLast;
    __shared__ double sv[8];
    __shared__ float  sdp[8];
    __shared__ float  spnew[8];

    const float BND = 0.99609375f;       // 1 - 2/512 exactly
    const float INVH = 1.0f / 255.5f;

    for (int it = 0; it < NITER; it++) {
        // --- read current p (L2, other SM may have written it) ---
        if (tid < 8) sp[tid] = __ldcg(&g_p[b][tid]);
        __syncthreads();
        float p0 = sp[0], p1 = sp[1], p2 = sp[2];
        float p3 = sp[3], p4 = sp[4], p5 = sp[5];
        // p6 = p7 = 0 exactly (reference zeroes dp[6:8]); den == 1

        float acc[8];
#pragma unroll
        for (int c = 0; c < 8; c++) acc[c] = 0.0f;

        for (int q = blockIdx.x * 256 + tid; q < NQUAD; q += NBLK * 256) {
            int i = q << 2;
            int x = i & (WI - 1), y = i >> 9;
            float Yc = (float)y - 255.5f;

            float4 Tc = *reinterpret_cast<const float4*>(T + i);
            int yU = y > 0      ? y - 1 : 0;
            int yD = y < HI - 1 ? y + 1 : HI - 1;
            float4 TU = *reinterpret_cast<const float4*>(T + yU * WI + x);
            float4 TD = *reinterpret_cast<const float4*>(T + yD * WI + x);
            float Tm1 = (x > 0)      ? __ldg(T + i - 1) : Tc.x;
            float Tp4 = (x < WI - 4) ? __ldg(T + i + 4) : Tc.w;

            float Tca[4] = {Tc.x, Tc.y, Tc.z, Tc.w};
            float gxa[4] = {0.5f * (Tc.y - Tm1), 0.5f * (Tc.z - Tc.x),
                            0.5f * (Tc.w - Tc.y), 0.5f * (Tp4 - Tc.z)};
            float gya[4] = {0.5f * (TD.x - TU.x), 0.5f * (TD.y - TU.y),
                            0.5f * (TD.z - TU.z), 0.5f * (TD.w - TU.w)};

#pragma unroll
            for (int j = 0; j < 4; j++) {
                float X = (float)(x + j) - 255.5f;
                float Xw = (1.0f + p0) * X + p1 * Yc + p2 + 255.5f;
                float Yw = p3 * X + (1.0f + p4) * Yc + p5 + 255.5f;

                float x0f = floorf(Xw), y0f = floorf(Yw);
                float wx = Xw - x0f, wy = Yw - y0f;
                float x0c = fminf(fmaxf(x0f, -2.0f), 513.0f);
                float y0c = fminf(fmaxf(y0f, -2.0f), 513.0f);
                int x0 = (int)x0c, y0 = (int)y0c;
                bool vx0 = (x0 >= 0) && (x0 <= WI - 1);
                bool vx1 = (x0 + 1 >= 0) && (x0 + 1 <= WI - 1);
                bool vy0 = (y0 >= 0) && (y0 <= HI - 1);
                bool vy1 = (y0 + 1 >= 0) && (y0 + 1 <= HI - 1);
                int xi0 = min(max(x0, 0), WI - 1), xi1 = min(max(x0 + 1, 0), WI - 1);
                int yi0 = min(max(y0, 0), HI - 1), yi1 = min(max(y0 + 1, 0), HI - 1);

                float v = 0.0f;
                if (vx0 && vy0) v += __ldg(I + yi0 * WI + xi0) * ((1.0f - wx) * (1.0f - wy));
                if (vx1 && vy0) v += __ldg(I + yi0 * WI + xi1) * (wx * (1.0f - wy));
                if (vx0 && vy1) v += __ldg(I + yi1 * WI + xi0) * ((1.0f - wx) * wy);
                if (vx1 && vy1) v += __ldg(I + yi1 * WI + xi1) * (wx * wy);

                float xn = Xw * INVH - 1.0f;
                float yn = Yw * INVH - 1.0f;
                float mask = (xn > -BND && xn < BND && yn > -BND && yn < BND) ? 1.0f : 0.0f;

                float r = v - Tca[j] * mask;
                float gr_x = gxa[j] * r;
                float gr_y = gya[j] * r;
                float t = X * gr_x + Yc * gr_y;

                acc[0] += X * gr_x;
                acc[1] += Yc * gr_x;
                acc[2] += gr_x;
                acc[3] += X * gr_y;
                acc[4] += Yc * gr_y;
                acc[5] += gr_y;
                acc[6] -= X * t;
                acc[7] -= Yc * t;
            }
        }

        // --- block tree reduction ---
#pragma unroll
        for (int c = 0; c < 8; c++)
            for (int off = 16; off > 0; off >>= 1)
                acc[c] += __shfl_down_sync(FULL, acc[c], off);
        if (lane == 0)
#pragma unroll
            for (int c = 0; c < 8; c++) swp[wid][c] = acc[c];
        __syncthreads();
        if (tid < 8) {
            float s = 0.0f;
#pragma unroll
            for (int w = 0; w < 8; w++) s += swp[w][tid];
            g_partR[b][blockIdx.x][tid] = s;
        }

        // --- arrive ---
        __threadfence();
        __syncthreads();
        if (tid == 0)
            sLast = ((atomicAdd(&g_sem[b], 1u) + 1u) % NBLK) == 0u;
        __syncthreads();

        if (sLast) {
            // reduce partials: warp w handles channel w (bypass L1)
            if (wid < 8) {
                double s = 0.0;
                for (int i = lane; i < NBLK; i += 32)
                    s += (double)__ldcg(&g_partR[b][i][wid]);
                for (int off = 16; off > 0; off >>= 1)
                    s += __shfl_down_sync(FULL, s, off);
                if (lane == 0) sv[wid] = s;
            }
            if (tid < 8) sdp[tid] = __ldcg(&g_dp[b][tid]);
            __syncthreads();

            if (tid < 8) {
                int i = tid;
                double n2 = 0.0;
#pragma unroll
                for (int j = 0; j < 8; j++) { double d = (double)sdp[j]; n2 += d * d; }
                bool gate = sqrt(n2) > 1e-3;
                double d = 0.0;
#pragma unroll
                for (int j = 0; j < 8; j++) d += g_invH[b][i][j] * sv[j];
                if (i >= 6) d = 0.0;             // no projective update
                float dpf = gate ? (float)d : 0.0f;
                float pn = sp[i] - dpf;
                g_dp[b][i] = dpf;
                g_p[b][i]  = pn;
                spnew[i] = pn;
            }
            __syncthreads();

            if (it == NITER - 1) {
                // write output: p [B,8] then H [B,3,3]
                if (tid < 8) {
                    int idx = b * 8 + tid;
                    if (idx < out_size) out[idx] = spnew[tid];
                }
                if (tid < 9) {
                    float m[9] = {1.0f + spnew[0], spnew[1], spnew[2],
                                  spnew[3], 1.0f + spnew[4], spnew[5],
                                  spnew[6], spnew[7], 1.0f};
                    int idx = NB * 8 + b * 9 + tid;
                    if (idx < out_size) out[idx] = m[tid];
                }
            }
            __threadfence();
            __syncthreads();
            if (tid == 0) g_gen[b] = (unsigned)(it + 1);
        }

        // --- wait for release ---
        if (tid == 0) {
            while (g_gen[b] < (unsigned)(it + 1)) __nanosleep(64);
        }
        __syncthreads();
        __threadfence();
    }
}

extern "C" void kernel_launch(void* const* d_in, const int* in_sizes, int n_in,
                              void* d_out, int out_size) {
    const float* img  = (const float*)d_in[0];
    const float* temp = (const float*)d_in[1];
    float* out = (float*)d_out;

    kGram<<<dim3(NBLK, NB), 256>>>(temp);
    kInvInit<<<NB, 64>>>();
    kPersist<<<dim3(NBLK, NB), 256>>>(img, temp, out, out_size);
}

// round 5
// speedup vs baseline: 7.3713x; 1.0721x over previous
#include <cuda_runtime.h>
#include <math.h>

// DeepLK inverse-compositional LK homography solve — single persistent kernel.
// img, temp: [8,1,512,512] f32. Output: p [8,8,1] then H [8,3,3] = 136 floats.

#define WI 512
#define HI 512
#define NPIX (WI*HI)
#define NQUAD (NPIX/4)
#define NB 8
#define NBLK 64                 // blocks per batch; grid (64,8)=512 <= 148*4 resident
#define NTHR 256
#define STRIDE (NBLK*NTHR)      // 16384 quads; NQUAD/STRIDE == 4 exactly
#define NITER 10

__device__ float        g_partR[NB][NBLK][8];
__device__ float        g_partH[NB][NBLK][36];
__device__ unsigned int g_sem[NB];

// ---- packed f32x2 helpers (B300 FFMA2 path) ----
__device__ __forceinline__ unsigned long long pk2(float lo, float hi) {
    unsigned long long r;
    asm("mov.b64 %0, {%1, %2};" : "=l"(r) : "f"(lo), "f"(hi));
    return r;
}
__device__ __forceinline__ void upk2(unsigned long long v, float& lo, float& hi) {
    asm("mov.b64 {%0, %1}, %2;" : "=f"(lo), "=f"(hi) : "l"(v));
}
__device__ __forceinline__ unsigned long long ffma2(unsigned long long a,
                                                    unsigned long long b,
                                                    unsigned long long c) {
    unsigned long long r;
    asm("fma.rn.f32x2 %0, %1, %2, %3;" : "=l"(r) : "l"(a), "l"(b), "l"(c));
    return r;
}
__device__ __forceinline__ unsigned long long fadd2(unsigned long long a,
                                                    unsigned long long b) {
    unsigned long long r;
    asm("add.rn.f32x2 %0, %1, %2;" : "=l"(r) : "l"(a), "l"(b));
    return r;
}

__global__ void kZero() { if (threadIdx.x < NB) g_sem[threadIdx.x] = 0u; }

// per-batch software barrier: cumulative arrivals; all blocks poll the counter
__device__ __forceinline__ void batch_barrier(int b, unsigned target) {
    __threadfence();
    __syncthreads();
    if (threadIdx.x == 0) {
        atomicAdd(&g_sem[b], 1u);
        while (*(volatile unsigned int*)&g_sem[b] < target) __nanosleep(64);
    }
    __syncthreads();
}

__global__ void __launch_bounds__(NTHR, 4)
kPersist(const float* __restrict__ img, const float* __restrict__ temp,
         float* __restrict__ out, int out_size) {
    int b = blockIdx.y;
    const float* I = img  + (size_t)b * NPIX;
    const float* T = temp + (size_t)b * NPIX;
    int tid = threadIdx.x;
    int wid = tid >> 5, lane = tid & 31;
    unsigned FULL = 0xffffffffu;
    int qbase = blockIdx.x * NTHR + tid;

    __shared__ double sH[36];
    __shared__ double sA[8][16];
    __shared__ double sInv[8][8];
    __shared__ double sv[8];
    __shared__ float  sp[8], sdp[8];
    __shared__ float  swp[8][8];
    __shared__ float  swh[8][36];

    // =======================================================================
    // Phase 0: Gram partials  Hm = J^T J (36 unique entries)
    // =======================================================================
    {
        float acc[36];
#pragma unroll
        for (int c = 0; c < 36; c++) acc[c] = 0.0f;

#pragma unroll
        for (int u = 0; u < 4; u++) {
            int q = qbase + u * STRIDE;
            int i = q << 2;
            int x = i & (WI - 1), y = i >> 9;
            float Yc = (float)y - 255.5f;
            float4 Tc = *reinterpret_cast<const float4*>(T + i);
            int yU = y > 0      ? y - 1 : 0;
            int yD = y < HI - 1 ? y + 1 : HI - 1;
            float4 TU = *reinterpret_cast<const float4*>(T + yU * WI + x);
            float4 TD = *reinterpret_cast<const float4*>(T + yD * WI + x);
            float Tm1 = (x > 0)      ? __ldg(T + i - 1) : Tc.x;
            float Tp4 = (x < WI - 4) ? __ldg(T + i + 4) : Tc.w;

            float gxa[4] = {0.5f * (Tc.y - Tm1), 0.5f * (Tc.z - Tc.x),
                            0.5f * (Tc.w - Tc.y), 0.5f * (Tp4 - Tc.z)};
            float gya[4] = {0.5f * (TD.x - TU.x), 0.5f * (TD.y - TU.y),
                            0.5f * (TD.z - TU.z), 0.5f * (TD.w - TU.w)};
#pragma unroll
            for (int j = 0; j < 4; j++) {
                float X = (float)(x + j) - 255.5f;
                float gx = gxa[j], gy = gya[j];
                float s = X * gx + Yc * gy;
                float a[8];
                a[0] = X * gx; a[1] = Yc * gx; a[2] = gx;
                a[3] = X * gy; a[4] = Yc * gy; a[5] = gy;
                a[6] = -X * s; a[7] = -Yc * s;
                int c = 0;
#pragma unroll
                for (int ii = 0; ii < 8; ii++)
#pragma unroll
                    for (int jj = ii; jj < 8; jj++)
                        acc[c++] += a[ii] * a[jj];
            }
        }

#pragma unroll
        for (int c = 0; c < 36; c++)
            for (int off = 16; off > 0; off >>= 1)
                acc[c] += __shfl_down_sync(FULL, acc[c], off);
        if (lane == 0)
#pragma unroll
            for (int c = 0; c < 36; c++) swh[wid][c] = acc[c];
        __syncthreads();
        if (tid < 36) {
            float s = 0.0f;
#pragma unroll
            for (int w = 0; w < 8; w++) s += swh[w][tid];
            g_partH[b][blockIdx.x][tid] = s;
        }
    }

    batch_barrier(b, NBLK);

    // every block redundantly (deterministically) reduces + inverts
    if (tid < 36) {
        double s = 0.0;
        for (int i = 0; i < NBLK; i++) s += (double)__ldcg(&g_partH[b][i][tid]);
        sH[tid] = s;
    }
    if (tid < 8) { sp[tid] = 0.0f; sdp[tid] = 1.0f; }
    __syncthreads();
    if (tid == 0) {
        int c = 0;
        for (int i = 0; i < 8; i++)
            for (int j = i; j < 8; j++) { sA[i][j] = sH[c]; sA[j][i] = sH[c]; c++; }
        for (int i = 0; i < 8; i++)
            for (int j = 0; j < 8; j++) sA[i][8 + j] = (i == j) ? 1.0 : 0.0;
        for (int col = 0; col < 8; col++) {
            int piv = col; double mx = fabs(sA[col][col]);
            for (int r = col + 1; r < 8; r++) {
                double v = fabs(sA[r][col]);
                if (v > mx) { mx = v; piv = r; }
            }
            if (piv != col)
                for (int j = 0; j < 16; j++) {
                    double tmp = sA[col][j]; sA[col][j] = sA[piv][j]; sA[piv][j] = tmp;
                }
            double inv = 1.0 / sA[col][col];
            for (int j = 0; j < 16; j++) sA[col][j] *= inv;
            for (int r = 0; r < 8; r++)
                if (r != col) {
                    double f = sA[r][col];
                    for (int j = 0; j < 16; j++) sA[r][j] -= f * sA[col][j];
                }
        }
        for (int i = 0; i < 8; i++)
            for (int j = 0; j < 8; j++) sInv[i][j] = sA[i][8 + j];
    }
    __syncthreads();

    // =======================================================================
    // LK iterations
    // =======================================================================
    for (int it = 0; it < NITER; it++) {
        float p0 = sp[0], p1 = sp[1], p2 = sp[2];
        float p3 = sp[3], p4 = sp[4], p5 = sp[5];
        // p6 = p7 = 0 exactly (reference zeroes dp[6:8]); den == 1

        unsigned long long PA = pk2(1.0f + p0, p3);
        unsigned long long PB = pk2(p1, 1.0f + p4);
        unsigned long long PC = pk2(p2 + 255.5f, p5 + 255.5f);

        unsigned long long acc01 = 0, acc34 = 0, acc25 = 0, acc67 = 0; // f32x2 zeros

        const float BND = 0.99609375f;        // 1 - 2/512 exactly
        const float INVH = 1.0f / 255.5f;

#pragma unroll
        for (int u = 0; u < 4; u++) {
            int q = qbase + u * STRIDE;
            int i = q << 2;
            int x = i & (WI - 1), y = i >> 9;
            float Yc = (float)y - 255.5f;

            float4 Tc = *reinterpret_cast<const float4*>(T + i);
            int yU = y > 0      ? y - 1 : 0;
            int yD = y < HI - 1 ? y + 1 : HI - 1;
            float4 TU = *reinterpret_cast<const float4*>(T + yU * WI + x);
            float4 TD = *reinterpret_cast<const float4*>(T + yD * WI + x);
            float Tm1 = (x > 0)      ? __ldg(T + i - 1) : Tc.x;
            float Tp4 = (x < WI - 4) ? __ldg(T + i + 4) : Tc.w;

            float Tca[4] = {Tc.x, Tc.y, Tc.z, Tc.w};
            float gxa[4] = {0.5f * (Tc.y - Tm1), 0.5f * (Tc.z - Tc.x),
                            0.5f * (Tc.w - Tc.y), 0.5f * (Tp4 - Tc.z)};
            float gya[4] = {0.5f * (TD.x - TU.x), 0.5f * (TD.y - TU.y),
                            0.5f * (TD.z - TU.z), 0.5f * (TD.w - TU.w)};

            unsigned long long WB = ffma2(pk2(Yc, Yc), PB, PC); // per-quad hoist

#pragma unroll
            for (int j = 0; j < 4; j++) {
                float X = (float)(x + j) - 255.5f;
                float Xw, Yw;
                upk2(ffma2(pk2(X, X), PA, WB), Xw, Yw);

                float x0f = floorf(Xw), y0f = floorf(Yw);
                float wx = Xw - x0f, wy = Yw - y0f;
                float w00 = (1.0f - wx) * (1.0f - wy);
                float w10 = wx * (1.0f - wy);
                float w01 = (1.0f - wx) * wy;
                float w11 = wx * wy;

                float v, mask;
                bool fast = (Xw >= 1.0f) & (Xw <= 509.0f) &
                            (Yw >= 1.0f) & (Yw <= 509.0f);
                if (fast) {
                    // all taps valid, mask == 1
                    const float* base = I + ((int)y0f) * WI + (int)x0f;
                    v = 0.0f;
                    v += __ldg(base)          * w00;
                    v += __ldg(base + 1)      * w10;
                    v += __ldg(base + WI)     * w01;
                    v += __ldg(base + WI + 1) * w11;
                    mask = 1.0f;
                } else {
                    float x0c = fminf(fmaxf(x0f, -2.0f), 513.0f);
                    float y0c = fminf(fmaxf(y0f, -2.0f), 513.0f);
                    int x0 = (int)x0c, y0 = (int)y0c;
                    bool vx0 = (x0 >= 0) && (x0 <= WI - 1);
                    bool vx1 = (x0 + 1 >= 0) && (x0 + 1 <= WI - 1);
                    bool vy0 = (y0 >= 0) && (y0 <= HI - 1);
                    bool vy1 = (y0 + 1 >= 0) && (y0 + 1 <= HI - 1);
                    int xi0 = min(max(x0, 0), WI - 1), xi1 = min(max(x0 + 1, 0), WI - 1);
                    int yi0 = min(max(y0, 0), HI - 1), yi1 = min(max(y0 + 1, 0), HI - 1);
                    v = 0.0f;
                    if (vx0 && vy0) v += __ldg(I + yi0 * WI + xi0) * w00;
                    if (vx1 && vy0) v += __ldg(I + yi0 * WI + xi1) * w10;
                    if (vx0 && vy1) v += __ldg(I + yi1 * WI + xi0) * w01;
                    if (vx1 && vy1) v += __ldg(I + yi1 * WI + xi1) * w11;
                    float xn = Xw * INVH - 1.0f;
                    float yn = Yw * INVH - 1.0f;
                    mask = (xn > -BND && xn < BND && yn > -BND && yn < BND) ? 1.0f : 0.0f;
                }

                float r = v - Tca[j] * mask;
                float gr_x = gxa[j] * r;
                float gr_y = gya[j] * r;
                float t = X * gr_x + Yc * gr_y;

                unsigned long long XY = pk2(X, Yc);
                acc01 = ffma2(XY, pk2(gr_x, gr_x), acc01);
                acc34 = ffma2(XY, pk2(gr_y, gr_y), acc34);
                acc25 = fadd2(acc25, pk2(gr_x, gr_y));
                acc67 = ffma2(XY, pk2(-t, -t), acc67);
            }
        }

        float acc[8];
        upk2(acc01, acc[0], acc[1]);
        upk2(acc34, acc[3], acc[4]);
        upk2(acc25, acc[2], acc[5]);
        upk2(acc67, acc[6], acc[7]);

        // --- block tree reduction ---
#pragma unroll
        for (int c = 0; c < 8; c++)
            for (int off = 16; off > 0; off >>= 1)
                acc[c] += __shfl_down_sync(FULL, acc[c], off);
        if (lane == 0)
#pragma unroll
            for (int c = 0; c < 8; c++) swp[wid][c] = acc[c];
        __syncthreads();
        if (tid < 8) {
            float s = 0.0f;
#pragma unroll
            for (int w = 0; w < 8; w++) s += swp[w][tid];
            g_partR[b][blockIdx.x][tid] = s;
        }

        batch_barrier(b, (unsigned)(NBLK * (it + 2)));

        // every block redundantly reduces partials: warp w handles channel w
        if (wid < 8) {
            double s = 0.0;
            for (int i = lane; i < NBLK; i += 32)
                s += (double)__ldcg(&g_partR[b][i][wid]);
            for (int off = 16; off > 0; off >>= 1)
                s += __shfl_down_sync(FULL, s, off);
            if (lane == 0) sv[wid] = s;
        }
        __syncthreads();

        if (tid < 8) {
            int i = tid;
            double n2 = 0.0;
#pragma unroll
            for (int j = 0; j < 8; j++) { double d = (double)sdp[j]; n2 += d * d; }
            bool gate = sqrt(n2) > 1e-3;
            double d = 0.0;
#pragma unroll
            for (int j = 0; j < 8; j++) d += sInv[i][j] * sv[j];
            if (i >= 6) d = 0.0;                 // no projective update
            float dpf = gate ? (float)d : 0.0f;
            __syncwarp(0x000000ffu);             // norm reads done before writes
            sdp[i] = dpf;
            sp[i]  = sp[i] - dpf;
        }
        __syncthreads();
    }

    // output: p [B,8] then H [B,3,3], written by block x==0 of each batch
    if (blockIdx.x == 0) {
        if (tid < 8) {
            int idx = b * 8 + tid;
            if (idx < out_size) out[idx] = sp[tid];
        }
        if (tid < 9) {
            float m[9] = {1.0f + sp[0], sp[1], sp[2],
                          sp[3], 1.0f + sp[4], sp[5],
                          sp[6], sp[7], 1.0f};
            int idx = NB * 8 + b * 9 + tid;
            if (idx < out_size) out[idx] = m[tid];
        }
    }
}

extern "C" void kernel_launch(void* const* d_in, const int* in_sizes, int n_in,
                              void* d_out, int out_size) {
    const float* img  = (const float*)d_in[0];
    const float* temp = (const float*)d_in[1];
    float* out = (float*)d_out;

    kZero<<<1, 32>>>();
    kPersist<<<dim3(NBLK, NB), NTHR>>>(img, temp, out, out_size);
}